// round 3
// baseline (speedup 1.0000x reference)
#include <cuda_runtime.h>

// ---------------------------------------------------------------------------
// Fused IGCNet conv: 3 launches, each fully fuses
//   edge MLP (gather+concat -> 40->64 relu -> 64->32 relu)
//   segment max (contiguous: node i owns edges [16i,16i+16))
//   node MLP (concat(x,aggr)=64 -> 64 relu -> 16 relu), norm clip, concat x[:,:16]
// Block = 256 threads = 16 nodes = 256 edges.
// edge_index is int32 (JAX default x64-disabled).
// R3: node MLP rewritten with float4 operand loads (was ~450 scalar LDS/thread,
//     now ~200 wavefronts) — kernel is L1/shared-wavefront bound per ncu.
// ---------------------------------------------------------------------------

#define NMAX 100000
__device__ float g_buf0[(size_t)NMAX * 32];
__device__ float g_buf1[(size_t)NMAX * 32];

// shared memory layout (float offsets)
#define OFF_W1T   0                 // [40][64]  w1_1 transposed
#define OFF_B1    2560              // [64]
#define OFF_W2T   2624              // [64][32]  w1_2 transposed
#define OFF_B2    4672              // [32]
#define OFF_W3T   4704              // [64][64]  w2_1 transposed
#define OFF_B3    8800              // [64]
#define OFF_W4    8864              // [16][64]  w2_2 ROW-major (o-major)
#define OFF_B4    9888              // [16]
#define OFF_XIN   9904              // [16][64]  per-node [x_i(32) | aggr(32)]
#define OFF_U     10928             // union: A[40][256] then H[64][HS] then hid[16][64]
#define HS        260               // H row stride (conflict-free .128 stores)
#define SMEM_FLOATS (OFF_U + 64 * HS)

__global__ void __launch_bounds__(256, 2) conv_kernel(
    const float* __restrict__ h_in, float* __restrict__ h_out,
    const int* __restrict__ src, const float* __restrict__ edge_attr,
    const float* __restrict__ w11, const float* __restrict__ b11,
    const float* __restrict__ w12, const float* __restrict__ b12,
    const float* __restrict__ w21, const float* __restrict__ b21,
    const float* __restrict__ w22, const float* __restrict__ b22)
{
    extern __shared__ float s[];
    const int tid = threadIdx.x;

    // ---- stage weights ----
    for (int i = tid; i < 2560; i += 256) { int k = i >> 6, h = i & 63; s[OFF_W1T + k * 64 + h] = w11[h * 40 + k]; }
    for (int i = tid; i < 2048; i += 256) { int k = i >> 5, o = i & 31; s[OFF_W2T + k * 32 + o] = w12[o * 64 + k]; }
    for (int i = tid; i < 4096; i += 256) { int k = i >> 6, h = i & 63; s[OFF_W3T + k * 64 + h] = w21[h * 64 + k]; }
    for (int i = tid; i < 1024; i += 256) { s[OFF_W4 + i] = w22[i]; }   // row-major copy
    if (tid < 64) s[OFF_B1 + tid] = b11[tid];
    if (tid < 32) s[OFF_B2 + tid] = b12[tid];
    if (tid < 64) s[OFF_B3 + tid] = b21[tid];
    if (tid < 16) s[OFF_B4 + tid] = b22[tid];

    const int n0 = blockIdx.x * 16;

    // ---- gather: A[k][e] tile, k-major, stride 256 (thread = one edge) ----
    {
        const long long eg = (long long)blockIdx.x * 256 + tid;
        const int si = src[eg];
        const float4* xr = (const float4*)(h_in + (size_t)si * 32);
        #pragma unroll
        for (int j = 0; j < 8; j++) {
            float4 v = xr[j];
            s[OFF_U + (4 * j + 0) * 256 + tid] = v.x;
            s[OFF_U + (4 * j + 1) * 256 + tid] = v.y;
            s[OFF_U + (4 * j + 2) * 256 + tid] = v.z;
            s[OFF_U + (4 * j + 3) * 256 + tid] = v.w;
        }
        const float4* ar = (const float4*)(edge_attr + (size_t)eg * 8);
        #pragma unroll
        for (int j = 0; j < 2; j++) {
            float4 v = ar[j];
            s[OFF_U + (32 + 4 * j + 0) * 256 + tid] = v.x;
            s[OFF_U + (32 + 4 * j + 1) * 256 + tid] = v.y;
            s[OFF_U + (32 + 4 * j + 2) * 256 + tid] = v.z;
            s[OFF_U + (32 + 4 * j + 3) * 256 + tid] = v.w;
        }
        if (tid < 128) {  // destination-node features -> Xin[:, 0:32]
            int nd = tid >> 3, q = tid & 7;
            float4 v = *(const float4*)(h_in + (size_t)(n0 + nd) * 32 + q * 4);
            *(float4*)&s[OFF_XIN + nd * 64 + q * 4] = v;
        }
    }
    __syncthreads();

    // ---- GEMM1: [256 edges, 40] x [40, 64] -> hidden, 8x8 register tile ----
    const int eg = tid >> 3;         // 0..31, edges eg*8..eg*8+7
    const int hg = tid & 7;          // 0..7,  hidden hg*8..hg*8+7
    const int e0 = eg * 8, h0 = hg * 8;
    float acc[8][8];
    #pragma unroll
    for (int i = 0; i < 8; i++) {
        float b = s[OFF_B1 + h0 + i];
        #pragma unroll
        for (int j = 0; j < 8; j++) acc[i][j] = b;
    }
    #pragma unroll 4
    for (int k = 0; k < 40; k++) {
        const float4 a0 = *(const float4*)&s[OFF_U + k * 256 + e0];
        const float4 a1 = *(const float4*)&s[OFF_U + k * 256 + e0 + 4];
        const float4 q0 = *(const float4*)&s[OFF_W1T + k * 64 + h0];
        const float4 q1 = *(const float4*)&s[OFF_W1T + k * 64 + h0 + 4];
        const float aa[8] = {a0.x, a0.y, a0.z, a0.w, a1.x, a1.y, a1.z, a1.w};
        const float ww[8] = {q0.x, q0.y, q0.z, q0.w, q1.x, q1.y, q1.z, q1.w};
        #pragma unroll
        for (int i = 0; i < 8; i++)
            #pragma unroll
            for (int j = 0; j < 8; j++)
                acc[i][j] = fmaf(ww[i], aa[j], acc[i][j]);
    }
    __syncthreads();   // all A reads done; U is reused as H
    #pragma unroll
    for (int i = 0; i < 8; i++) {
        float4 v0 = make_float4(fmaxf(acc[i][0], 0.f), fmaxf(acc[i][1], 0.f),
                                fmaxf(acc[i][2], 0.f), fmaxf(acc[i][3], 0.f));
        float4 v1 = make_float4(fmaxf(acc[i][4], 0.f), fmaxf(acc[i][5], 0.f),
                                fmaxf(acc[i][6], 0.f), fmaxf(acc[i][7], 0.f));
        *(float4*)&s[OFF_U + (h0 + i) * HS + e0]     = v0;
        *(float4*)&s[OFF_U + (h0 + i) * HS + e0 + 4] = v1;
    }
    __syncthreads();

    // ---- GEMM2: [256, 64] x [64, 32] -> msg, relu, max over 16-edge segs ---
    const int og = tid & 7, o0 = og * 4;   // same eg as GEMM1
    float acc2[8][4];
    #pragma unroll
    for (int c = 0; c < 4; c++) {
        float b = s[OFF_B2 + o0 + c];
        #pragma unroll
        for (int j = 0; j < 8; j++) acc2[j][c] = b;
    }
    #pragma unroll 4
    for (int k = 0; k < 64; k++) {
        const float4 hA = *(const float4*)&s[OFF_U + k * HS + e0];
        const float4 hB = *(const float4*)&s[OFF_U + k * HS + e0 + 4];
        const float4 wv = *(const float4*)&s[OFF_W2T + k * 32 + o0];
        const float hh[8] = {hA.x, hA.y, hA.z, hA.w, hB.x, hB.y, hB.z, hB.w};
        const float wwv[4] = {wv.x, wv.y, wv.z, wv.w};
        #pragma unroll
        for (int j = 0; j < 8; j++)
            #pragma unroll
            for (int c = 0; c < 4; c++)
                acc2[j][c] = fmaf(hh[j], wwv[c], acc2[j][c]);
    }
    // relu + max over this thread's 8 edges (relu folds into max with 0 init)
    float mx[4] = {0.f, 0.f, 0.f, 0.f};
    #pragma unroll
    for (int j = 0; j < 8; j++)
        #pragma unroll
        for (int c = 0; c < 4; c++)
            mx[c] = fmaxf(mx[c], acc2[j][c]);
    // combine with partner (tid^8 shares the other 8 edges of this node)
    #pragma unroll
    for (int c = 0; c < 4; c++)
        mx[c] = fmaxf(mx[c], __shfl_xor_sync(0xffffffffu, mx[c], 8));
    if (!(eg & 1)) {
        int nd = eg >> 1;
        *(float4*)&s[OFF_XIN + nd * 64 + 32 + o0] = make_float4(mx[0], mx[1], mx[2], mx[3]);
    }
    __syncthreads();   // Xin complete; H dead -> U reused as hid[16][64]

    // ---- node MLP (vectorized): layer1 thread = (node, 4-col tile) ----
    {
        const int nd = tid >> 4;          // 0..15 (half-warp per node)
        const int q  = tid & 15;
        const int c4 = q * 4;             // layer1 output cols c4..c4+3

        float ha[4];
        #pragma unroll
        for (int j = 0; j < 4; j++) ha[j] = s[OFF_B3 + c4 + j];
        #pragma unroll
        for (int k4 = 0; k4 < 16; k4++) {
            const float4 xv = *(const float4*)&s[OFF_XIN + nd * 64 + k4 * 4];
            const float xx[4] = {xv.x, xv.y, xv.z, xv.w};
            #pragma unroll
            for (int kk = 0; kk < 4; kk++) {
                const float4 wv = *(const float4*)&s[OFF_W3T + (k4 * 4 + kk) * 64 + c4];
                ha[0] = fmaf(xx[kk], wv.x, ha[0]);
                ha[1] = fmaf(xx[kk], wv.y, ha[1]);
                ha[2] = fmaf(xx[kk], wv.z, ha[2]);
                ha[3] = fmaf(xx[kk], wv.w, ha[3]);
            }
        }
        *(float4*)&s[OFF_U + nd * 64 + c4] = make_float4(
            fmaxf(ha[0], 0.f), fmaxf(ha[1], 0.f), fmaxf(ha[2], 0.f), fmaxf(ha[3], 0.f));
        __syncwarp();   // hid row written by same half-warp that reads it

        // layer2: thread = (node, output o); both operands float4
        const int o = q;
        float a3 = s[OFF_B4 + o];
        #pragma unroll
        for (int k4 = 0; k4 < 16; k4++) {
            const float4 hv = *(const float4*)&s[OFF_U + nd * 64 + k4 * 4];
            const float4 wv = *(const float4*)&s[OFF_W4 + o * 64 + k4 * 4];
            a3 = fmaf(hv.x, wv.x, a3);
            a3 = fmaf(hv.y, wv.y, a3);
            a3 = fmaf(hv.z, wv.z, a3);
            a3 = fmaf(hv.w, wv.w, a3);
        }
        float v = fmaxf(a3, 0.f);
        // norm clip over the 16 outputs of this node (16-lane subgroup)
        float ss = v * v;
        ss += __shfl_xor_sync(0xffffffffu, ss, 1);
        ss += __shfl_xor_sync(0xffffffffu, ss, 2);
        ss += __shfl_xor_sync(0xffffffffu, ss, 4);
        ss += __shfl_xor_sync(0xffffffffu, ss, 8);
        const float sn = sqrtf(ss);
        if (sn > 1.f) v = v / sn;
        const size_t ng = (size_t)(n0 + nd);
        h_out[ng * 32 + o]      = v;
        h_out[ng * 32 + 16 + o] = s[OFF_XIN + nd * 64 + o];  // x[:, :16]
    }
}

extern "C" void kernel_launch(void* const* d_in, const int* in_sizes, int n_in,
                              void* d_out, int out_size)
{
    const float* x     = (const float*)d_in[0];
    const int*   eidx  = (const int*)d_in[1];     // [2, E] int32
    const float* eattr = (const float*)d_in[2];
    const float* w11 = (const float*)d_in[3];
    const float* b11 = (const float*)d_in[4];
    const float* w12 = (const float*)d_in[5];
    const float* b12 = (const float*)d_in[6];
    const float* w21 = (const float*)d_in[7];
    const float* b21 = (const float*)d_in[8];
    const float* w22 = (const float*)d_in[9];
    const float* b22 = (const float*)d_in[10];

    const int nN = in_sizes[0] / 32;          // 100000
    const int* srcp = eidx;                   // row 0 = src
    const int grid = nN / 16;                 // 6250 blocks (16 nodes each)
    const size_t smem = (size_t)SMEM_FLOATS * sizeof(float);

    cudaFuncSetAttribute(conv_kernel, cudaFuncAttributeMaxDynamicSharedMemorySize, (int)smem);

    float *b0, *b1;
    cudaGetSymbolAddress((void**)&b0, g_buf0);
    cudaGetSymbolAddress((void**)&b1, g_buf1);

    conv_kernel<<<grid, 256, smem>>>(x,  b0, srcp, eattr, w11, b11, w12, b12, w21, b21, w22, b22);
    conv_kernel<<<grid, 256, smem>>>(b0, b1, srcp, eattr, w11, b11, w12, b12, w21, b21, w22, b22);
    conv_kernel<<<grid, 256, smem>>>(b1, (float*)d_out, srcp, eattr, w11, b11, w12, b12, w21, b21, w22, b22);
}

// round 7
// speedup vs baseline: 1.2957x; 1.2957x over previous
#include <cuda_runtime.h>
#include <cstdint>

// ---------------------------------------------------------------------------
// Fused IGCNet conv, mma.sync tf32 (3xTF32 split) edition. 3 launches.
// Per block: 16 nodes, 256 edges, 8 warps (warp w owns edges 32w..32w+31).
//   GEMM1: A[256,40] x W1[64,40]^T via m16n8k8 tf32 (3x split) -> H
//   GEMM2: H[256,64] x W2[32,64]^T -> msg; relu+bias fused at stores
//   segment max (16 contiguous edges/node) -> aggr
//   node MLP fp32 SIMT (64->64 relu ->16 relu), norm clip, concat x[:,:16]
// tcgen05 is unavailable (harness targets compute_100, no 'a' features);
// mma.sync is baseline PTX (sm_80+) and runs on the tensor pipe.
// ---------------------------------------------------------------------------

#define NMAX 100000
__device__ float g_buf0[(size_t)NMAX * 32];
__device__ float g_buf1[(size_t)NMAX * 32];

// ---- smem layout (float offsets). U is a phase-union region. ----
#define OFF_U     0        // phase1: A1[256][41] + W1s[64][41]; phase2: H[256][67]; phase3: msg[256][35]
#define OFF_W1S   10496    // inside U
#define OFF_W2S   17152    // W2s[32][67] = 2144; later hid[16][64]
#define OFF_XIN   19296    // [16][64] = [x_i(32) | aggr(32)]
#define OFF_W3T   20320    // [64][64] w2_1 transposed
#define OFF_B1    24416
#define OFF_B2    24480
#define OFF_B3    24512
#define OFF_B4    24576
#define SMEM_FLOATS 24592  // 98368 bytes -> occupancy 2

__device__ __forceinline__ uint32_t f2tf(float f) {
    uint32_t u;
    asm("cvt.rna.tf32.f32 %0, %1;" : "=r"(u) : "f"(f));
    return u;
}
__device__ __forceinline__ void split_tf(float f, uint32_t& hi, uint32_t& lo) {
    hi = f2tf(f);
    lo = f2tf(f - __uint_as_float(hi));
}
__device__ __forceinline__ void mma8(float* c, const uint32_t* a, const uint32_t* b) {
    asm volatile(
        "mma.sync.aligned.m16n8k8.row.col.f32.tf32.tf32.f32 "
        "{%0,%1,%2,%3}, {%4,%5,%6,%7}, {%8,%9}, {%0,%1,%2,%3};"
        : "+f"(c[0]), "+f"(c[1]), "+f"(c[2]), "+f"(c[3])
        : "r"(a[0]), "r"(a[1]), "r"(a[2]), "r"(a[3]), "r"(b[0]), "r"(b[1]));
}

__global__ void __launch_bounds__(256, 2) conv_kernel(
    const float* __restrict__ h_in, float* __restrict__ h_out,
    const int* __restrict__ src, const float* __restrict__ edge_attr,
    const float* __restrict__ w11, const float* __restrict__ b11,
    const float* __restrict__ w12, const float* __restrict__ b12,
    const float* __restrict__ w21, const float* __restrict__ b21,
    const float* __restrict__ w22, const float* __restrict__ b22)
{
    extern __shared__ float s[];
    const int tid = threadIdx.x;
    const int wid = tid >> 5, l = tid & 31;
    const int n0 = blockIdx.x * 16;

    // ---- stage weights (full fp32; hi/lo computed at use) ----
    for (int i = tid; i < 2560; i += 256) { int n = i / 40, k = i - 40 * n; s[OFF_W1S + n * 41 + k] = w11[i]; }
    for (int i = tid; i < 2048; i += 256) { int n = i >> 6, k = i & 63; s[OFF_W2S + n * 67 + k] = w12[i]; }
    for (int i = tid; i < 4096; i += 256) { int k = i >> 6, h = i & 63; s[OFF_W3T + k * 64 + h] = w21[h * 64 + k]; }
    if (tid < 64) s[OFF_B1 + tid] = b11[tid];
    if (tid < 32) s[OFF_B2 + tid] = b12[tid];
    if (tid < 64) s[OFF_B3 + tid] = b21[tid];
    if (tid < 16) s[OFF_B4 + tid] = b22[tid];

    // ---- gather: A1[e][k] row-major stride 41 (odd -> conflict-free stores) ----
    {
        const long long eg = (long long)blockIdx.x * 256 + tid;
        const int si = src[eg];
        const float4* xr = (const float4*)(h_in + (size_t)si * 32);
        const int base = OFF_U + tid * 41;
        #pragma unroll
        for (int j = 0; j < 8; j++) {
            float4 v = xr[j];
            s[base + 4 * j + 0] = v.x; s[base + 4 * j + 1] = v.y;
            s[base + 4 * j + 2] = v.z; s[base + 4 * j + 3] = v.w;
        }
        const float4* ar = (const float4*)(edge_attr + (size_t)eg * 8);
        #pragma unroll
        for (int j = 0; j < 2; j++) {
            float4 v = ar[j];
            s[base + 32 + 4 * j + 0] = v.x; s[base + 32 + 4 * j + 1] = v.y;
            s[base + 32 + 4 * j + 2] = v.z; s[base + 32 + 4 * j + 3] = v.w;
        }
        if (tid < 128) {  // destination-node features -> Xin[:, 0:32]
            int nd = tid >> 3, q = tid & 7;
            float4 v = *(const float4*)(h_in + (size_t)(n0 + nd) * 32 + q * 4);
            *(float4*)&s[OFF_XIN + nd * 64 + q * 4] = v;
        }
    }
    __syncthreads();

    const int e0 = 32 * wid;
    const int lr = l >> 2, lc = l & 3;   // fragment row-group / col-in-group

    // ---- GEMM1: [256,40] x W1^T -> acc[2 mt][8 nt][4], 3xTF32 ----
    float acc[2][8][4];
    #pragma unroll
    for (int mt = 0; mt < 2; mt++)
        #pragma unroll
        for (int nt = 0; nt < 8; nt++)
            #pragma unroll
            for (int q = 0; q < 4; q++) acc[mt][nt][q] = 0.f;

    #pragma unroll
    for (int kc = 0; kc < 5; kc++) {
        uint32_t ah[2][4], al[2][4];
        #pragma unroll
        for (int mt = 0; mt < 2; mt++) {
            const int rb = OFF_U + (e0 + 16 * mt + lr) * 41 + 8 * kc + lc;
            split_tf(s[rb],            ah[mt][0], al[mt][0]);
            split_tf(s[rb + 8 * 41],   ah[mt][1], al[mt][1]);
            split_tf(s[rb + 4],        ah[mt][2], al[mt][2]);
            split_tf(s[rb + 8 * 41 + 4], ah[mt][3], al[mt][3]);
        }
        #pragma unroll
        for (int nt = 0; nt < 8; nt++) {
            const int wb = OFF_W1S + (8 * nt + lr) * 41 + 8 * kc + lc;
            uint32_t bh[2], bl[2];
            split_tf(s[wb],     bh[0], bl[0]);
            split_tf(s[wb + 4], bh[1], bl[1]);
            #pragma unroll
            for (int mt = 0; mt < 2; mt++) {
                mma8(acc[mt][nt], ah[mt], bh);
                mma8(acc[mt][nt], al[mt], bh);
                mma8(acc[mt][nt], ah[mt], bl);
            }
        }
    }
    __syncthreads();   // all warps done reading A1/W1s; U becomes H[256][67]

    // ---- H = relu(acc + b1) -> smem ----
    #pragma unroll
    for (int mt = 0; mt < 2; mt++) {
        const int r0 = e0 + 16 * mt + lr;
        #pragma unroll
        for (int nt = 0; nt < 8; nt++) {
            const int c0 = 8 * nt + 2 * lc;
            const float bv0 = s[OFF_B1 + c0], bv1 = s[OFF_B1 + c0 + 1];
            s[OFF_U + r0 * 67 + c0]           = fmaxf(acc[mt][nt][0] + bv0, 0.f);
            s[OFF_U + r0 * 67 + c0 + 1]       = fmaxf(acc[mt][nt][1] + bv1, 0.f);
            s[OFF_U + (r0 + 8) * 67 + c0]     = fmaxf(acc[mt][nt][2] + bv0, 0.f);
            s[OFF_U + (r0 + 8) * 67 + c0 + 1] = fmaxf(acc[mt][nt][3] + bv1, 0.f);
        }
    }
    __syncthreads();

    // ---- GEMM2: H[256,64] x W2^T -> acc2[2][4][4], 3xTF32 ----
    float acc2[2][4][4];
    #pragma unroll
    for (int mt = 0; mt < 2; mt++)
        #pragma unroll
        for (int nt = 0; nt < 4; nt++)
            #pragma unroll
            for (int q = 0; q < 4; q++) acc2[mt][nt][q] = 0.f;

    #pragma unroll
    for (int kc = 0; kc < 8; kc++) {
        uint32_t ah[2][4], al[2][4];
        #pragma unroll
        for (int mt = 0; mt < 2; mt++) {
            const int rb = OFF_U + (e0 + 16 * mt + lr) * 67 + 8 * kc + lc;
            split_tf(s[rb],             ah[mt][0], al[mt][0]);
            split_tf(s[rb + 8 * 67],    ah[mt][1], al[mt][1]);
            split_tf(s[rb + 4],         ah[mt][2], al[mt][2]);
            split_tf(s[rb + 8 * 67 + 4], ah[mt][3], al[mt][3]);
        }
        #pragma unroll
        for (int nt = 0; nt < 4; nt++) {
            const int wb = OFF_W2S + (8 * nt + lr) * 67 + 8 * kc + lc;
            uint32_t bh[2], bl[2];
            split_tf(s[wb],     bh[0], bl[0]);
            split_tf(s[wb + 4], bh[1], bl[1]);
            #pragma unroll
            for (int mt = 0; mt < 2; mt++) {
                mma8(acc2[mt][nt], ah[mt], bh);
                mma8(acc2[mt][nt], al[mt], bh);
                mma8(acc2[mt][nt], ah[mt], bl);
            }
        }
    }
    __syncthreads();   // all warps done reading H; U becomes msg[256][35]

    // ---- msg = relu(acc2 + b2) -> smem ----
    #pragma unroll
    for (int mt = 0; mt < 2; mt++) {
        const int r0 = e0 + 16 * mt + lr;
        #pragma unroll
        for (int nt = 0; nt < 4; nt++) {
            const int c0 = 8 * nt + 2 * lc;
            const float bv0 = s[OFF_B2 + c0], bv1 = s[OFF_B2 + c0 + 1];
            s[OFF_U + r0 * 35 + c0]           = fmaxf(acc2[mt][nt][0] + bv0, 0.f);
            s[OFF_U + r0 * 35 + c0 + 1]       = fmaxf(acc2[mt][nt][1] + bv1, 0.f);
            s[OFF_U + (r0 + 8) * 35 + c0]     = fmaxf(acc2[mt][nt][2] + bv0, 0.f);
            s[OFF_U + (r0 + 8) * 35 + c0 + 1] = fmaxf(acc2[mt][nt][3] + bv1, 0.f);
        }
    }
    __syncthreads();

    // ---- segment max (16 edges/node) -> XIN[:, 32:64] ----
    {
        const int nd = tid >> 4, o = tid & 15;
        float a0 = 0.f, a1 = 0.f;   // msg >= 0 post-relu
        #pragma unroll
        for (int rr = 0; rr < 16; rr++) {
            const int base = OFF_U + (16 * nd + rr) * 35;
            a0 = fmaxf(a0, s[base + o]);
            a1 = fmaxf(a1, s[base + 16 + o]);
        }
        s[OFF_XIN + nd * 64 + 32 + o] = a0;
        s[OFF_XIN + nd * 64 + 48 + o] = a1;
    }
    __syncthreads();

    // ---- node MLP (fp32 SIMT): thread = (node nd, part q) ----
    {
        const int nd = tid >> 4, q = tid & 15;
        const int c4 = q * 4;
        float ha[4];
        #pragma unroll
        for (int j = 0; j < 4; j++) ha[j] = s[OFF_B3 + c4 + j];
        #pragma unroll
        for (int k4 = 0; k4 < 16; k4++) {
            const float4 xv = *(const float4*)&s[OFF_XIN + nd * 64 + k4 * 4];
            const float xx[4] = {xv.x, xv.y, xv.z, xv.w};
            #pragma unroll
            for (int kk = 0; kk < 4; kk++) {
                const float4 wv = *(const float4*)&s[OFF_W3T + (k4 * 4 + kk) * 64 + c4];
                ha[0] = fmaf(xx[kk], wv.x, ha[0]);
                ha[1] = fmaf(xx[kk], wv.y, ha[1]);
                ha[2] = fmaf(xx[kk], wv.z, ha[2]);
                ha[3] = fmaf(xx[kk], wv.w, ha[3]);
            }
        }
        // hid[16][64] aliases W2s region (dead after GEMM2)
        *(float4*)&s[OFF_W2S + nd * 64 + c4] = make_float4(
            fmaxf(ha[0], 0.f), fmaxf(ha[1], 0.f), fmaxf(ha[2], 0.f), fmaxf(ha[3], 0.f));
        __syncwarp();

        const int o = q;
        float a3 = s[OFF_B4 + o];
        #pragma unroll
        for (int k4 = 0; k4 < 16; k4++) {
            const float4 hv = *(const float4*)&s[OFF_W2S + nd * 64 + k4 * 4];
            const float4 wv = __ldg((const float4*)(w22 + o * 64 + k4 * 4));
            a3 = fmaf(hv.x, wv.x, a3);
            a3 = fmaf(hv.y, wv.y, a3);
            a3 = fmaf(hv.z, wv.z, a3);
            a3 = fmaf(hv.w, wv.w, a3);
        }
        float v = fmaxf(a3, 0.f);
        float ssq = v * v;
        ssq += __shfl_xor_sync(0xffffffffu, ssq, 1);
        ssq += __shfl_xor_sync(0xffffffffu, ssq, 2);
        ssq += __shfl_xor_sync(0xffffffffu, ssq, 4);
        ssq += __shfl_xor_sync(0xffffffffu, ssq, 8);
        const float sn = sqrtf(ssq);
        if (sn > 1.f) v = v / sn;
        const size_t ng = (size_t)(n0 + nd);
        h_out[ng * 32 + o]      = v;
        h_out[ng * 32 + 16 + o] = s[OFF_XIN + nd * 64 + o];  // x[:, :16]
    }
}

extern "C" void kernel_launch(void* const* d_in, const int* in_sizes, int n_in,
                              void* d_out, int out_size)
{
    const float* x     = (const float*)d_in[0];
    const int*   eidx  = (const int*)d_in[1];     // [2, E] int32
    const float* eattr = (const float*)d_in[2];
    const float* w11 = (const float*)d_in[3];
    const float* b11 = (const float*)d_in[4];
    const float* w12 = (const float*)d_in[5];
    const float* b12 = (const float*)d_in[6];
    const float* w21 = (const float*)d_in[7];
    const float* b21 = (const float*)d_in[8];
    const float* w22 = (const float*)d_in[9];
    const float* b22 = (const float*)d_in[10];

    const int nN = in_sizes[0] / 32;          // 100000
    const int* srcp = eidx;                   // row 0 = src
    const int grid = nN / 16;                 // 6250 blocks
    const size_t smem = (size_t)SMEM_FLOATS * sizeof(float);

    cudaFuncSetAttribute(conv_kernel, cudaFuncAttributeMaxDynamicSharedMemorySize, (int)smem);

    float *b0, *b1;
    cudaGetSymbolAddress((void**)&b0, g_buf0);
    cudaGetSymbolAddress((void**)&b1, g_buf1);

    conv_kernel<<<grid, 256, smem>>>(x,  b0, srcp, eattr, w11, b11, w12, b12, w21, b21, w22, b22);
    conv_kernel<<<grid, 256, smem>>>(b0, b1, srcp, eattr, w11, b11, w12, b12, w21, b21, w22, b22);
    conv_kernel<<<grid, 256, smem>>>(b1, (float*)d_out, srcp, eattr, w11, b11, w12, b12, w21, b21, w22, b22);
}

// round 9
// speedup vs baseline: 1.3560x; 1.0465x over previous
#include <cuda_runtime.h>
#include <cstdint>

// ---------------------------------------------------------------------------
// Fused IGCNet conv, mma.sync 3xTF32, 128-edge blocks, swizzled smem.
// Block: 8 nodes, 128 edges, 4 warps. Occupancy 4 (47.7KB smem).
//   GEMM1: A[128,40] x W1[64,40]^T -> H[128,64]   (m16n8k8 tf32, 3x split)
//   GEMM2: H[128,64] x W2[32,64]^T -> msgT[32,128]
//   segment max (16 edges/node) -> aggr; node MLP fp32 SIMT; norm clip.
// All GEMM fragment loads/stores conflict-free via XOR swizzle (col bits 2-4).
// R9: identical resubmission of R8 (container failure was diagnostic-free;
//     discriminating infra flake vs deterministic failure).
// ---------------------------------------------------------------------------

#define NMAX 100000
__device__ float g_buf0[(size_t)NMAX * 32];
__device__ float g_buf1[(size_t)NMAX * 32];

// ---- smem layout (float offsets) ----
// U (9216): phase1 A[128][40](5120)+W1[64][40](2560); phase2 H[128][72];
//           phase3 msgT[32][132](4224)+W3[64][72](4608)
#define OFF_U     0
#define OFF_W1    5120
#define OFF_W3    4224
#define OFF_W2S   9216     // [32][72] = 2304; later hid[8][64]
#define OFF_XIN   11520    // [8][64]
#define OFF_B1    12032
#define OFF_B2    12096
#define OFF_B3    12128
#define OFF_B4    12192
#define SMEM_FLOATS 12208  // 48832 B -> 4 blocks/SM

__device__ __forceinline__ uint32_t f2tf(float f) {
    uint32_t u;
    asm("cvt.rna.tf32.f32 %0, %1;" : "=r"(u) : "f"(f));
    return u;
}
__device__ __forceinline__ void split_tf(float f, uint32_t& hi, uint32_t& lo) {
    hi = f2tf(f);
    lo = f2tf(f - __uint_as_float(hi));
}
__device__ __forceinline__ void mma8(float* c, const uint32_t* a, const uint32_t* b) {
    asm volatile(
        "mma.sync.aligned.m16n8k8.row.col.f32.tf32.tf32.f32 "
        "{%0,%1,%2,%3}, {%4,%5,%6,%7}, {%8,%9}, {%0,%1,%2,%3};"
        : "+f"(c[0]), "+f"(c[1]), "+f"(c[2]), "+f"(c[3])
        : "r"(a[0]), "r"(a[1]), "r"(a[2]), "r"(a[3]), "r"(b[0]), "r"(b[1]));
}
// swizzle for 40-col tiles (A, W1): cols 0..31 3-bit XOR, cols 32..39 1-bit
__device__ __forceinline__ int swA(int c, int x) {
    return (c < 32) ? (c ^ x) : (32 + ((c - 32) ^ (x & 4)));
}

__global__ void __launch_bounds__(128, 4) conv_kernel(
    const float* __restrict__ h_in, float* __restrict__ h_out,
    const int* __restrict__ src, const float* __restrict__ edge_attr,
    const float* __restrict__ w11, const float* __restrict__ b11,
    const float* __restrict__ w12, const float* __restrict__ b12,
    const float* __restrict__ w21, const float* __restrict__ b21,
    const float* __restrict__ w22, const float* __restrict__ b22)
{
    extern __shared__ float s[];
    const int tid = threadIdx.x;
    const int wid = tid >> 5, l = tid & 31;
    const int n0 = blockIdx.x * 8;

    // ---- stage W1/W2 (swizzled) + biases ----
    for (int i = tid; i < 2560; i += 128) {
        int n = i / 40, k = i - 40 * n;
        s[OFF_W1 + n * 40 + swA(k, ((n >> 2) & 7) << 2)] = w11[i];
    }
    for (int i = tid; i < 2048; i += 128) {
        int n = i >> 6, k = i & 63;
        s[OFF_W2S + n * 72 + (k ^ (((n >> 2) & 7) << 2))] = w12[i];
    }
    if (tid < 64) s[OFF_B1 + tid] = b11[tid];
    if (tid < 32) s[OFF_B2 + tid] = b12[tid];
    if (tid < 64) s[OFF_B3 + tid] = b21[tid];
    if (tid < 16) s[OFF_B4 + tid] = b22[tid];

    // ---- gather: A[e][k] stride 40 swizzled (thread = edge) ----
    {
        const long long eg = (long long)blockIdx.x * 128 + tid;
        const int si = src[eg];
        const float4* xr = (const float4*)(h_in + (size_t)si * 32);
        const int xa = ((tid >> 2) & 7) << 2;
        const int rb = OFF_U + tid * 40;
        #pragma unroll
        for (int j = 0; j < 8; j++)
            *(float4*)&s[rb + ((4 * j) ^ xa)] = xr[j];
        const float4* ar = (const float4*)(edge_attr + (size_t)eg * 8);
        #pragma unroll
        for (int j = 0; j < 2; j++)
            *(float4*)&s[rb + 32 + ((4 * j) ^ (xa & 4))] = ar[j];
        if (tid < 64) {  // destination-node features -> Xin[:, 0:32]
            int nd = tid >> 3, q = tid & 7;
            float4 v = *(const float4*)(h_in + (size_t)(n0 + nd) * 32 + q * 4);
            *(float4*)&s[OFF_XIN + nd * 64 + q * 4] = v;
        }
    }
    __syncthreads();

    const int e0 = 32 * wid;
    const int lr = l >> 2, lc = l & 3;
    // per-mt row bases + swizzle masks (rows r0, r0+8)
    int r0m[2], r1m[2], x0m[2], x1m[2];
    #pragma unroll
    for (int mt = 0; mt < 2; mt++) {
        r0m[mt] = e0 + 16 * mt + lr;
        r1m[mt] = r0m[mt] + 8;
        x0m[mt] = ((r0m[mt] >> 2) & 7) << 2;
        x1m[mt] = ((r1m[mt] >> 2) & 7) << 2;
    }

    // ---- GEMM1: A[128,40] x W1^T -> acc[2][8][4], 3xTF32 ----
    float acc[2][8][4];
    #pragma unroll
    for (int mt = 0; mt < 2; mt++)
        #pragma unroll
        for (int nt = 0; nt < 8; nt++)
            #pragma unroll
            for (int q = 0; q < 4; q++) acc[mt][nt][q] = 0.f;

    #pragma unroll
    for (int kc = 0; kc < 5; kc++) {
        const int c0 = 8 * kc + lc, c1 = c0 + 4;
        uint32_t ah[2][4], al[2][4];
        #pragma unroll
        for (int mt = 0; mt < 2; mt++) {
            split_tf(s[OFF_U + r0m[mt] * 40 + swA(c0, x0m[mt])], ah[mt][0], al[mt][0]);
            split_tf(s[OFF_U + r1m[mt] * 40 + swA(c0, x1m[mt])], ah[mt][1], al[mt][1]);
            split_tf(s[OFF_U + r0m[mt] * 40 + swA(c1, x0m[mt])], ah[mt][2], al[mt][2]);
            split_tf(s[OFF_U + r1m[mt] * 40 + swA(c1, x1m[mt])], ah[mt][3], al[mt][3]);
        }
        #pragma unroll
        for (int nt = 0; nt < 8; nt++) {
            const int wr = 8 * nt + lr;
            const int xw = ((wr >> 2) & 7) << 2;
            uint32_t bh[2], bl[2];
            split_tf(s[OFF_W1 + wr * 40 + swA(c0, xw)], bh[0], bl[0]);
            split_tf(s[OFF_W1 + wr * 40 + swA(c1, xw)], bh[1], bl[1]);
            #pragma unroll
            for (int mt = 0; mt < 2; mt++) {
                mma8(acc[mt][nt], ah[mt], bh);
                mma8(acc[mt][nt], al[mt], bh);
                mma8(acc[mt][nt], ah[mt], bl);
            }
        }
    }
    __syncthreads();   // A/W1 reads done; U becomes H[128][72]

    // ---- H = relu(acc + b1) -> swizzled smem (float2 stores) ----
    #pragma unroll
    for (int mt = 0; mt < 2; mt++) {
        #pragma unroll
        for (int nt = 0; nt < 8; nt++) {
            const int c0 = 8 * nt + 2 * lc;
            const float bv0 = s[OFF_B1 + c0], bv1 = s[OFF_B1 + c0 + 1];
            float2 v01 = make_float2(fmaxf(acc[mt][nt][0] + bv0, 0.f),
                                     fmaxf(acc[mt][nt][1] + bv1, 0.f));
            float2 v23 = make_float2(fmaxf(acc[mt][nt][2] + bv0, 0.f),
                                     fmaxf(acc[mt][nt][3] + bv1, 0.f));
            *(float2*)&s[OFF_U + r0m[mt] * 72 + (c0 ^ x0m[mt])] = v01;
            *(float2*)&s[OFF_U + r1m[mt] * 72 + (c0 ^ x1m[mt])] = v23;
        }
    }
    __syncthreads();

    // ---- GEMM2: H[128,64] x W2^T -> acc2[2][4][4], 3xTF32 ----
    float acc2[2][4][4];
    #pragma unroll
    for (int mt = 0; mt < 2; mt++)
        #pragma unroll
        for (int nt = 0; nt < 4; nt++)
            #pragma unroll
            for (int q = 0; q < 4; q++) acc2[mt][nt][q] = 0.f;

    #pragma unroll
    for (int kc = 0; kc < 8; kc++) {
        const int c0 = 8 * kc + lc, c1 = c0 + 4;
        uint32_t ah[2][4], al[2][4];
        #pragma unroll
        for (int mt = 0; mt < 2; mt++) {
            split_tf(s[OFF_U + r0m[mt] * 72 + (c0 ^ x0m[mt])], ah[mt][0], al[mt][0]);
            split_tf(s[OFF_U + r1m[mt] * 72 + (c0 ^ x1m[mt])], ah[mt][1], al[mt][1]);
            split_tf(s[OFF_U + r0m[mt] * 72 + (c1 ^ x0m[mt])], ah[mt][2], al[mt][2]);
            split_tf(s[OFF_U + r1m[mt] * 72 + (c1 ^ x1m[mt])], ah[mt][3], al[mt][3]);
        }
        #pragma unroll
        for (int nt = 0; nt < 4; nt++) {
            const int wr = 8 * nt + lr;
            const int xw = ((wr >> 2) & 7) << 2;
            uint32_t bh[2], bl[2];
            split_tf(s[OFF_W2S + wr * 72 + (c0 ^ xw)], bh[0], bl[0]);
            split_tf(s[OFF_W2S + wr * 72 + (c1 ^ xw)], bh[1], bl[1]);
            #pragma unroll
            for (int mt = 0; mt < 2; mt++) {
                mma8(acc2[mt][nt], ah[mt], bh);
                mma8(acc2[mt][nt], al[mt], bh);
                mma8(acc2[mt][nt], ah[mt], bl);
            }
        }
    }
    __syncthreads();   // H reads done; U becomes msgT[32][132] + W3[64][72]

    // ---- msg = relu(acc2 + b2) -> msgT[c][e] (conflict-free scalar stores) ----
    #pragma unroll
    for (int mt = 0; mt < 2; mt++) {
        #pragma unroll
        for (int nt = 0; nt < 4; nt++) {
            const int c0 = 8 * nt + 2 * lc;
            const float bv0 = s[OFF_B2 + c0], bv1 = s[OFF_B2 + c0 + 1];
            s[OFF_U + c0 * 132 + r0m[mt]]       = fmaxf(acc2[mt][nt][0] + bv0, 0.f);
            s[OFF_U + (c0 + 1) * 132 + r0m[mt]] = fmaxf(acc2[mt][nt][1] + bv1, 0.f);
            s[OFF_U + c0 * 132 + r1m[mt]]       = fmaxf(acc2[mt][nt][2] + bv0, 0.f);
            s[OFF_U + (c0 + 1) * 132 + r1m[mt]] = fmaxf(acc2[mt][nt][3] + bv1, 0.f);
        }
    }
    // ---- stage W3 row-major swizzled (coalesced LDG, overlaps msg stores) ----
    for (int i4 = tid; i4 < 1024; i4 += 128) {
        const int h = i4 >> 4, cb = (i4 & 15) * 4;
        float4 v = __ldg((const float4*)(w21 + h * 64 + cb));
        *(float4*)&s[OFF_W3 + h * 72 + (cb ^ (((h >> 2) & 7) << 2))] = v;
    }
    __syncthreads();

    // ---- segment max (16 edges/node) -> XIN[:, 32:64] (vectorized) ----
    {
        const int nd = tid >> 4, o = tid & 15;
        float4 m0 = make_float4(0.f, 0.f, 0.f, 0.f);
        float4 m1 = make_float4(0.f, 0.f, 0.f, 0.f);
        #pragma unroll
        for (int q4 = 0; q4 < 4; q4++) {
            const float4 a = *(const float4*)&s[OFF_U + o * 132 + 16 * nd + 4 * q4];
            const float4 b = *(const float4*)&s[OFF_U + (16 + o) * 132 + 16 * nd + 4 * q4];
            m0.x = fmaxf(m0.x, a.x); m0.y = fmaxf(m0.y, a.y);
            m0.z = fmaxf(m0.z, a.z); m0.w = fmaxf(m0.w, a.w);
            m1.x = fmaxf(m1.x, b.x); m1.y = fmaxf(m1.y, b.y);
            m1.z = fmaxf(m1.z, b.z); m1.w = fmaxf(m1.w, b.w);
        }
        s[OFF_XIN + nd * 64 + 32 + o] = fmaxf(fmaxf(m0.x, m0.y), fmaxf(m0.z, m0.w));
        s[OFF_XIN + nd * 64 + 48 + o] = fmaxf(fmaxf(m1.x, m1.y), fmaxf(m1.z, m1.w));
        __syncwarp();

        // ---- node MLP: layer1 (outputs c4..c4+3 via row-major W3 dots) ----
        const int q = o, c4 = q * 4;
        const int xq = (q & 7) << 2;
        float ha[4];
        #pragma unroll
        for (int j = 0; j < 4; j++) ha[j] = s[OFF_B3 + c4 + j];
        #pragma unroll
        for (int k4 = 0; k4 < 16; k4++) {
            const float4 xv = *(const float4*)&s[OFF_XIN + nd * 64 + 4 * k4];
            #pragma unroll
            for (int j = 0; j < 4; j++) {
                const float4 wv = *(const float4*)&s[OFF_W3 + (c4 + j) * 72 + ((4 * k4) ^ xq)];
                ha[j] = fmaf(xv.x, wv.x, fmaf(xv.y, wv.y, fmaf(xv.z, wv.z, fmaf(xv.w, wv.w, ha[j]))));
            }
        }
        // hid[8][64] aliases W2S (dead after GEMM2)
        *(float4*)&s[OFF_W2S + nd * 64 + c4] = make_float4(
            fmaxf(ha[0], 0.f), fmaxf(ha[1], 0.f), fmaxf(ha[2], 0.f), fmaxf(ha[3], 0.f));
        __syncwarp();

        // ---- layer2 + norm clip + output ----
        float a3 = s[OFF_B4 + q];
        #pragma unroll
        for (int k4 = 0; k4 < 16; k4++) {
            const float4 hv = *(const float4*)&s[OFF_W2S + nd * 64 + 4 * k4];
            const float4 wv = __ldg((const float4*)(w22 + q * 64 + 4 * k4));
            a3 = fmaf(hv.x, wv.x, fmaf(hv.y, wv.y, fmaf(hv.z, wv.z, fmaf(hv.w, wv.w, a3))));
        }
        float v = fmaxf(a3, 0.f);
        float ssq = v * v;
        ssq += __shfl_xor_sync(0xffffffffu, ssq, 1);
        ssq += __shfl_xor_sync(0xffffffffu, ssq, 2);
        ssq += __shfl_xor_sync(0xffffffffu, ssq, 4);
        ssq += __shfl_xor_sync(0xffffffffu, ssq, 8);
        const float sn = sqrtf(ssq);
        if (sn > 1.f) v = v / sn;
        const size_t ng = (size_t)(n0 + nd);
        h_out[ng * 32 + q]      = v;
        h_out[ng * 32 + 16 + q] = s[OFF_XIN + nd * 64 + q];  // x[:, :16]
    }
}

extern "C" void kernel_launch(void* const* d_in, const int* in_sizes, int n_in,
                              void* d_out, int out_size)
{
    const float* x     = (const float*)d_in[0];
    const int*   eidx  = (const int*)d_in[1];     // [2, E] int32
    const float* eattr = (const float*)d_in[2];
    const float* w11 = (const float*)d_in[3];
    const float* b11 = (const float*)d_in[4];
    const float* w12 = (const float*)d_in[5];
    const float* b12 = (const float*)d_in[6];
    const float* w21 = (const float*)d_in[7];
    const float* b21 = (const float*)d_in[8];
    const float* w22 = (const float*)d_in[9];
    const float* b22 = (const float*)d_in[10];

    const int nN = in_sizes[0] / 32;          // 100000
    const int* srcp = eidx;                   // row 0 = src
    const int grid = nN / 8;                  // 12500 blocks (8 nodes each)
    const size_t smem = (size_t)SMEM_FLOATS * sizeof(float);

    cudaFuncSetAttribute(conv_kernel, cudaFuncAttributeMaxDynamicSharedMemorySize, (int)smem);

    float *b0, *b1;
    cudaGetSymbolAddress((void**)&b0, g_buf0);
    cudaGetSymbolAddress((void**)&b1, g_buf1);

    conv_kernel<<<grid, 128, smem>>>(x,  b0, srcp, eattr, w11, b11, w12, b12, w21, b21, w22, b22);
    conv_kernel<<<grid, 128, smem>>>(b0, b1, srcp, eattr, w11, b11, w12, b12, w21, b21, w22, b22);
    conv_kernel<<<grid, 128, smem>>>(b1, (float*)d_out, srcp, eattr, w11, b11, w12, b12, w21, b21, w22, b22);
}